// round 13
// baseline (speedup 1.0000x reference)
#include <cuda_runtime.h>
#include <cuda_fp16.h>
#include <cuda_bf16.h>
#include <cstdint>

// Problem constants
#define NTOK 16384
#define DIM  768
#define HID  768
#define COUT 2
#define NEXP 20

// GEMM1 tiling (fp16 HMMA single-pass, cp.async 4-stage pipeline, 256 threads)
#define BM 128
#define BN 256
#define BK 32                  // fp16 K elems per stage
#define NITER (DIM / BK)       // 24
#define SPAD 40                // padded smem row stride in fp16 (80B)
#define NSTAGE 4
#define ST_W  (BM * SPAD)                         // halfs offset of W tile
#define STAGE_HALFS (BM * SPAD + BN * SPAD)       // 15360
#define STAGE_BYTES (STAGE_HALFS * 2)             // 30720
#define SMEM_TOTAL (NSTAGE * STAGE_BYTES)         // 122880

// ---------------- device scratch ----------------
__device__ int    g_offsets[NEXP + 1];
__device__ int    g_sorted_idx[NTOK];
__device__ int    g_sorted_expert[NTOK];
__device__ __half g_h16[(size_t)NTOK * HID];               // hidden (fp16), 25 MB
__device__ __half g_xf[(size_t)NTOK * DIM];                // X in fp16
__device__ __half g_w1f[(size_t)NEXP * HID * DIM];         // W1^T fp16, [e][n][k]

__device__ __forceinline__ uint32_t smem_u32(const void* p) {
    uint32_t a;
    asm("{ .reg .u64 t; cvta.to.shared.u64 t, %1; cvt.u32.u64 %0, t; }" : "=r"(a) : "l"(p));
    return a;
}

#define CP16(dst, src) \
    asm volatile("cp.async.cg.shared.global [%0], [%1], 16;" :: "r"(dst), "l"(src))
#define CP_COMMIT() asm volatile("cp.async.commit_group;")

#define LDMX4(r0, r1, r2, r3, a) \
    asm volatile("ldmatrix.sync.aligned.m8n8.x4.shared.b16 {%0,%1,%2,%3}, [%4];" \
        : "=r"(r0), "=r"(r1), "=r"(r2), "=r"(r3) : "r"(a))

#define MMAF16(d, a, b) \
    asm volatile("mma.sync.aligned.m16n8k16.row.col.f32.f16.f16.f32 " \
        "{%0,%1,%2,%3}, {%4,%5,%6,%7}, {%8,%9}, {%0,%1,%2,%3};" \
        : "+f"((d)[0]), "+f"((d)[1]), "+f"((d)[2]), "+f"((d)[3]) \
        : "r"((a)[0]), "r"((a)[1]), "r"((a)[2]), "r"((a)[3]), "r"((b)[0]), "r"((b)[1]))

// -------- kernel 1: fused prologue (detect + hist + scan + scatter) --------
__global__ __launch_bounds__(1024) void k_prep(const int* __restrict__ idx32) {
    __shared__ int s_cnt[NEXP];
    __shared__ int s_off[NEXP + 1];
    __shared__ int s_is64;
    const int t = threadIdx.x, lane = t & 31;

    if (t < NEXP) s_cnt[t] = 0;
    if (t == 0) s_is64 = 1;
    __syncthreads();

    for (int i = t; i < NTOK; i += 1024)
        if ((i & 1) && idx32[i] != 0) s_is64 = 0;
    __syncthreads();
    const int is64 = s_is64;

    for (int n = t; n < NTOK; n += 1024) {
        int e = is64 ? (int)((const long long*)idx32)[n] : idx32[n];
        unsigned m = __match_any_sync(0xFFFFFFFFu, e);
        if (lane == (__ffs(m) - 1)) atomicAdd(&s_cnt[e], __popc(m));
    }
    __syncthreads();

    if (t == 0) {
        int off = 0;
        for (int e = 0; e < NEXP; e++) { s_off[e] = off; off += s_cnt[e]; }
        s_off[NEXP] = off;
    }
    __syncthreads();
    if (t <= NEXP) g_offsets[t] = s_off[t];
    if (t < NEXP)  s_cnt[t] = s_off[t];
    __syncthreads();

    for (int n = t; n < NTOK; n += 1024) {
        int e = is64 ? (int)((const long long*)idx32)[n] : idx32[n];
        unsigned m = __match_any_sync(0xFFFFFFFFu, e);
        int leader = __ffs(m) - 1;
        int rank = __popc(m & ((1u << lane) - 1));
        int base = 0;
        if (lane == leader) base = atomicAdd(&s_cnt[e], __popc(m));
        base = __shfl_sync(0xFFFFFFFFu, base, leader);
        int p = base + rank;
        g_sorted_idx[p] = n;
        g_sorted_expert[p] = e;
    }
}

// -------- kernel 2a: convert X to fp16 --------
__global__ __launch_bounds__(256) void k_convert_x(const float* __restrict__ X) {
    size_t i = ((size_t)blockIdx.x * 256 + threadIdx.x) * 4;
    if (i >= (size_t)NTOK * DIM) return;
    float4 v = *(const float4*)(X + i);
    unsigned short h[4];
    h[0] = __half_as_ushort(__float2half_rn(v.x));
    h[1] = __half_as_ushort(__float2half_rn(v.y));
    h[2] = __half_as_ushort(__float2half_rn(v.z));
    h[3] = __half_as_ushort(__float2half_rn(v.w));
    *(uint2*)(g_xf + i) = make_uint2((unsigned)h[0] | ((unsigned)h[1] << 16),
                                     (unsigned)h[2] | ((unsigned)h[3] << 16));
}

// -------- kernel 2b: transpose W1 -> [e][n][k] fp16 --------
__global__ __launch_bounds__(256) void k_split_w1(const float* __restrict__ W1) {
    __shared__ float tile[32][33];
    const int e = blockIdx.z;
    const int kt = blockIdx.y * 32;
    const int nt = blockIdx.x * 32;
    const float* src = W1 + (size_t)e * DIM * HID;

    for (int i = threadIdx.y; i < 32; i += 8)
        tile[i][threadIdx.x] = src[(size_t)(kt + i) * HID + nt + threadIdx.x];
    __syncthreads();

    for (int i = threadIdx.y; i < 32; i += 8) {
        float v = tile[threadIdx.x][i];
        size_t o = ((size_t)e * HID + nt + i) * DIM + kt + threadIdx.x;
        g_w1f[o] = __float2half_rn(v);
    }
}

// -------- kernel 3: grouped GEMM1, fp16 HMMA, 8 warps 64x64, 4-stage cp.async --------
// h_sorted[s,:] = relu( X16[tok(s),:] @ W16[e] + b1[e] ), fp32 accum, fp16 store.
// grid = (HID/BN=3, NTOK/BM, NEXP), 256 thr = 8 warps (2 M x 4 N), warp tile 64x64.
__global__ __launch_bounds__(256, 1) void k_gemm1(const float* __restrict__ b1)
{
    extern __shared__ __align__(16) __half dynsm[];
    const uint32_t smem0 = smem_u32(dynsm);

    const int e = blockIdx.z;
    const int seg_lo = g_offsets[e];
    const int cnt    = g_offsets[e + 1] - seg_lo;
    const int m0 = blockIdx.y * BM;
    if (m0 >= cnt) return;
    const int n0 = blockIdx.x * BN;
    const int tid  = threadIdx.x;
    const int wid  = tid >> 5;
    const int lane = tid & 31;

    const int wm = (wid >> 2) * 64;   // warp M offset (0 or 64)
    const int wn = (wid & 3) * 64;    // warp N offset (0,64,128,192)

    // global->smem cp.async mapping (256 threads, 6 x 16B each):
    //  X: thread (r = tid>>1, q = tid&1) loads X[r, q*16 .. q*16+15]  (2 CP16)
    //  W: thread tid loads full 32-elem k-row of W[n0+tid]            (4 CP16)
    const int r_ld = tid >> 1;
    const int q_ld = tid & 1;
    const int m_ld = m0 + r_ld;
    const int tok  = (m_ld < cnt) ? g_sorted_idx[seg_lo + m_ld] : g_sorted_idx[seg_lo];
    const __half* pX = g_xf + (size_t)tok * DIM + q_ld * 16;
    const __half* pW = g_w1f + ((size_t)e * HID + n0 + tid) * DIM;
    const uint32_t dX_off = (uint32_t)(r_ld * SPAD + q_ld * 16) * 2;   // bytes
    const uint32_t dW_off = (uint32_t)(tid * SPAD) * 2;

    // ldmatrix lane addressing (byte offsets within a stage; row stride 80B)
    const int a_row = wm + (lane & 15);
    const int a_kb  = (lane >> 4) * 16;
    const int b_row = wn + ((lane >> 4) & 1) * 8 + (lane & 7);
    const int b_kb  = ((lane >> 3) & 1) * 16;

    float acc[4][8][4];
    #pragma unroll
    for (int i = 0; i < 4; i++)
        #pragma unroll
        for (int j = 0; j < 8; j++)
            #pragma unroll
            for (int q = 0; q < 4; q++) acc[i][j][q] = 0.f;

    auto issue = [&](int c, int st) {
        const int kg = c * BK;
        const uint32_t sb = smem0 + st * STAGE_BYTES;
        CP16(sb + dX_off,                 pX + kg);
        CP16(sb + dX_off + 16,            pX + kg + 8);
        CP16(sb + ST_W * 2 + dW_off,      pW + kg);
        CP16(sb + ST_W * 2 + dW_off + 16, pW + kg + 8);
        CP16(sb + ST_W * 2 + dW_off + 32, pW + kg + 16);
        CP16(sb + ST_W * 2 + dW_off + 48, pW + kg + 24);
        CP_COMMIT();
    };

    issue(0, 0);
    issue(1, 1);
    issue(2, 2);

    int st = 0;
    for (int c = 0; c < NITER; c++) {
        if (c + 3 <= NITER - 1)      { asm volatile("cp.async.wait_group 2;" ::: "memory"); }
        else if (c + 2 <= NITER - 1) { asm volatile("cp.async.wait_group 1;" ::: "memory"); }
        else                         { asm volatile("cp.async.wait_group 0;" ::: "memory"); }
        __syncthreads();

        if (c + 3 < NITER) {
            int st3 = st + 3; if (st3 >= NSTAGE) st3 -= NSTAGE;
            issue(c + 3, st3);
        }

        const uint32_t sb = smem0 + st * STAGE_BYTES;
        const uint32_t bX = sb;
        const uint32_t bW = sb + ST_W * 2;

        #pragma unroll
        for (int ks = 0; ks < 2; ks++) {
            uint32_t fx[4][4], fw[8][2];
            #pragma unroll
            for (int mt = 0; mt < 4; mt++) {
                uint32_t oa = (uint32_t)((a_row + mt * 16) * (SPAD * 2) + ks * 32 + a_kb);
                LDMX4(fx[mt][0], fx[mt][1], fx[mt][2], fx[mt][3], bX + oa);
            }
            #pragma unroll
            for (int p = 0; p < 4; p++) {
                uint32_t ob = (uint32_t)((b_row + p * 16) * (SPAD * 2) + ks * 32 + b_kb);
                LDMX4(fw[2 * p][0], fw[2 * p][1], fw[2 * p + 1][0], fw[2 * p + 1][1], bW + ob);
            }
            #pragma unroll
            for (int mt = 0; mt < 4; mt++)
                #pragma unroll
                for (int nt = 0; nt < 8; nt++)
                    MMAF16(acc[mt][nt], fx[mt], fw[nt]);
        }

        st = st + 1; if (st >= NSTAGE) st -= NSTAGE;
    }

    // epilogue: bias + ReLU, half2 stores to g_h16 (sorted layout)
    #pragma unroll
    for (int nt = 0; nt < 8; nt++) {
        const int ncol = n0 + wn + nt * 8 + (lane & 3) * 2;
        const float bia0 = b1[e * HID + ncol];
        const float bia1 = b1[e * HID + ncol + 1];
        #pragma unroll
        for (int mt = 0; mt < 4; mt++) {
            int r0 = wm + mt * 16 + (lane >> 2);
            int ma = m0 + r0;
            if (ma < cnt) {
                float v0 = fmaxf(acc[mt][nt][0] + bia0, 0.f);
                float v1 = fmaxf(acc[mt][nt][1] + bia1, 0.f);
                *(__half2*)(g_h16 + (size_t)(seg_lo + ma) * HID + ncol) =
                    __floats2half2_rn(v0, v1);
            }
            int mb = ma + 8;
            if (mb < cnt) {
                float v0 = fmaxf(acc[mt][nt][2] + bia0, 0.f);
                float v1 = fmaxf(acc[mt][nt][3] + bia1, 0.f);
                *(__half2*)(g_h16 + (size_t)(seg_lo + mb) * HID + ncol) =
                    __floats2half2_rn(v0, v1);
            }
        }
    }
}

// -------- kernel 4: out[tok] = h_sorted[s] @ W2[e] + b2[e], one warp per token --------
__global__ __launch_bounds__(256) void k_gemm2(
    const float* __restrict__ W2,
    const float* __restrict__ b2,
    float* __restrict__ out)
{
    int gwarp = (blockIdx.x * blockDim.x + threadIdx.x) >> 5;
    int lane  = threadIdx.x & 31;
    if (gwarp >= NTOK) return;
    int s   = gwarp;
    int e   = g_sorted_expert[s];
    int tok = g_sorted_idx[s];
    const __half2* hrow = (const __half2*)(g_h16 + (size_t)s * HID);   // 384 half2
    const float*   w2   = W2 + (size_t)e * HID * COUT;

    float a0 = 0.f, a1 = 0.f;
    #pragma unroll 4
    for (int i = lane; i < HID / 2; i += 32) {
        float2 hv = __half22float2(hrow[i]);
        float4 w = *(const float4*)(w2 + i * 4);   // weights for h[2i], h[2i+1]
        a0 = fmaf(hv.x, w.x, a0);
        a1 = fmaf(hv.x, w.y, a1);
        a0 = fmaf(hv.y, w.z, a0);
        a1 = fmaf(hv.y, w.w, a1);
    }
    #pragma unroll
    for (int o = 16; o > 0; o >>= 1) {
        a0 += __shfl_xor_sync(0xFFFFFFFFu, a0, o);
        a1 += __shfl_xor_sync(0xFFFFFFFFu, a1, o);
    }
    if (lane == 0) {
        out[tok * 2 + 0] = a0 + b2[e * 2 + 0];
        out[tok * 2 + 1] = a1 + b2[e * 2 + 1];
    }
}

extern "C" void kernel_launch(void* const* d_in, const int* in_sizes, int n_in,
                              void* d_out, int out_size) {
    const float* X   = (const float*)d_in[0];      // [N, D]
    const void*  cid = d_in[1];                    // [N] int32 or int64
    const float* W1  = (const float*)d_in[2];      // [E, D, H]
    const float* b1  = (const float*)d_in[3];      // [E, H]
    const float* W2  = (const float*)d_in[4];      // [E, H, C]
    const float* b2  = (const float*)d_in[5];      // [E, C]
    float*       out = (float*)d_out;              // [N, C]

    cudaFuncSetAttribute(k_gemm1, cudaFuncAttributeMaxDynamicSharedMemorySize, SMEM_TOTAL);

    k_prep<<<1, 1024>>>((const int*)cid);
    k_convert_x<<<(int)(((size_t)NTOK * DIM / 4 + 255) / 256), 256>>>(X);
    k_split_w1<<<dim3(HID / 32, DIM / 32, NEXP), dim3(32, 8)>>>(W1);

    dim3 grid1(HID / BN, NTOK / BM, NEXP);
    k_gemm1<<<grid1, 256, SMEM_TOTAL>>>(b1);

    k_gemm2<<<(NTOK * 32 + 255) / 256, 256>>>(W2, b2, out);
}

// round 17
// speedup vs baseline: 1.0003x; 1.0003x over previous
#include <cuda_runtime.h>
#include <cuda_fp16.h>
#include <cuda_bf16.h>
#include <cstdint>

// Problem constants
#define NTOK 16384
#define DIM  768
#define HID  768
#define COUT 2
#define NEXP 20

// GEMM1 tiling (fp16 HMMA single-pass, cp.async 3-stage pipeline, BK=64)
#define BM 128
#define BN 256
#define BK 64                  // fp16 K elems per stage
#define NITER (DIM / BK)       // 12
#define SPAD 72                // padded smem row stride in fp16 (144B)
#define NSTAGE 3
#define ST_W  (BM * SPAD)                         // halfs offset of W tile
#define STAGE_HALFS (BM * SPAD + BN * SPAD)       // 27648
#define STAGE_BYTES (STAGE_HALFS * 2)             // 55296
#define SMEM_TOTAL (NSTAGE * STAGE_BYTES)         // 165888

// ---------------- device scratch ----------------
__device__ int    g_offsets[NEXP + 1];
__device__ int    g_sorted_idx[NTOK];
__device__ int    g_sorted_expert[NTOK];
__device__ __half g_h16[(size_t)NTOK * HID];               // hidden (fp16), 25 MB
__device__ __half g_xf[(size_t)NTOK * DIM];                // X in fp16
__device__ __half g_w1f[(size_t)NEXP * HID * DIM];         // W1^T fp16, [e][n][k]

__device__ __forceinline__ uint32_t smem_u32(const void* p) {
    uint32_t a;
    asm("{ .reg .u64 t; cvta.to.shared.u64 t, %1; cvt.u32.u64 %0, t; }" : "=r"(a) : "l"(p));
    return a;
}

#define CP16(dst, src) \
    asm volatile("cp.async.cg.shared.global [%0], [%1], 16;" :: "r"(dst), "l"(src))
#define CP_COMMIT() asm volatile("cp.async.commit_group;")

#define LDMX4(r0, r1, r2, r3, a) \
    asm volatile("ldmatrix.sync.aligned.m8n8.x4.shared.b16 {%0,%1,%2,%3}, [%4];" \
        : "=r"(r0), "=r"(r1), "=r"(r2), "=r"(r3) : "r"(a))

#define MMAF16(d, a, b) \
    asm volatile("mma.sync.aligned.m16n8k16.row.col.f32.f16.f16.f32 " \
        "{%0,%1,%2,%3}, {%4,%5,%6,%7}, {%8,%9}, {%0,%1,%2,%3};" \
        : "+f"((d)[0]), "+f"((d)[1]), "+f"((d)[2]), "+f"((d)[3]) \
        : "r"((a)[0]), "r"((a)[1]), "r"((a)[2]), "r"((a)[3]), "r"((b)[0]), "r"((b)[1]))

// -------- kernel 1: fused prologue (detect + hist + scan + scatter) --------
__global__ __launch_bounds__(1024) void k_prep(const int* __restrict__ idx32) {
    __shared__ int s_cnt[NEXP];
    __shared__ int s_off[NEXP + 1];
    __shared__ int s_is64;
    const int t = threadIdx.x, lane = t & 31;

    if (t < NEXP) s_cnt[t] = 0;
    if (t == 0) s_is64 = 1;
    __syncthreads();

    for (int i = t; i < NTOK; i += 1024)
        if ((i & 1) && idx32[i] != 0) s_is64 = 0;
    __syncthreads();
    const int is64 = s_is64;

    for (int n = t; n < NTOK; n += 1024) {
        int e = is64 ? (int)((const long long*)idx32)[n] : idx32[n];
        unsigned m = __match_any_sync(0xFFFFFFFFu, e);
        if (lane == (__ffs(m) - 1)) atomicAdd(&s_cnt[e], __popc(m));
    }
    __syncthreads();

    if (t == 0) {
        int off = 0;
        for (int e = 0; e < NEXP; e++) { s_off[e] = off; off += s_cnt[e]; }
        s_off[NEXP] = off;
    }
    __syncthreads();
    if (t <= NEXP) g_offsets[t] = s_off[t];
    if (t < NEXP)  s_cnt[t] = s_off[t];
    __syncthreads();

    for (int n = t; n < NTOK; n += 1024) {
        int e = is64 ? (int)((const long long*)idx32)[n] : idx32[n];
        unsigned m = __match_any_sync(0xFFFFFFFFu, e);
        int leader = __ffs(m) - 1;
        int rank = __popc(m & ((1u << lane) - 1));
        int base = 0;
        if (lane == leader) base = atomicAdd(&s_cnt[e], __popc(m));
        base = __shfl_sync(0xFFFFFFFFu, base, leader);
        int p = base + rank;
        g_sorted_idx[p] = n;
        g_sorted_expert[p] = e;
    }
}

// -------- kernel 2a: convert X to fp16 --------
__global__ __launch_bounds__(256) void k_convert_x(const float* __restrict__ X) {
    size_t i = ((size_t)blockIdx.x * 256 + threadIdx.x) * 4;
    if (i >= (size_t)NTOK * DIM) return;
    float4 v = *(const float4*)(X + i);
    unsigned short h[4];
    h[0] = __half_as_ushort(__float2half_rn(v.x));
    h[1] = __half_as_ushort(__float2half_rn(v.y));
    h[2] = __half_as_ushort(__float2half_rn(v.z));
    h[3] = __half_as_ushort(__float2half_rn(v.w));
    *(uint2*)(g_xf + i) = make_uint2((unsigned)h[0] | ((unsigned)h[1] << 16),
                                     (unsigned)h[2] | ((unsigned)h[3] << 16));
}

// -------- kernel 2b: transpose W1 -> [e][n][k] fp16 --------
__global__ __launch_bounds__(256) void k_split_w1(const float* __restrict__ W1) {
    __shared__ float tile[32][33];
    const int e = blockIdx.z;
    const int kt = blockIdx.y * 32;
    const int nt = blockIdx.x * 32;
    const float* src = W1 + (size_t)e * DIM * HID;

    for (int i = threadIdx.y; i < 32; i += 8)
        tile[i][threadIdx.x] = src[(size_t)(kt + i) * HID + nt + threadIdx.x];
    __syncthreads();

    for (int i = threadIdx.y; i < 32; i += 8) {
        float v = tile[threadIdx.x][i];
        size_t o = ((size_t)e * HID + nt + i) * DIM + kt + threadIdx.x;
        g_w1f[o] = __float2half_rn(v);
    }
}

// -------- kernel 3: grouped GEMM1, fp16 HMMA, 8 warps 64x64, BK=64, 3 stages --------
// h_sorted[s,:] = relu( X16[tok(s),:] @ W16[e] + b1[e] ), fp32 accum, fp16 store.
// grid = (HID/BN=3, NTOK/BM, NEXP), 256 thr = 8 warps (2 M x 4 N), warp tile 64x64.
__global__ __launch_bounds__(256, 1) void k_gemm1(const float* __restrict__ b1)
{
    extern __shared__ __align__(16) __half dynsm[];
    const uint32_t smem0 = smem_u32(dynsm);

    const int e = blockIdx.z;
    const int seg_lo = g_offsets[e];
    const int cnt    = g_offsets[e + 1] - seg_lo;
    const int m0 = blockIdx.y * BM;
    if (m0 >= cnt) return;
    const int n0 = blockIdx.x * BN;
    const int tid  = threadIdx.x;
    const int wid  = tid >> 5;
    const int lane = tid & 31;

    const int wm = (wid >> 2) * 64;   // warp M offset (0 or 64)
    const int wn = (wid & 3) * 64;    // warp N offset (0,64,128,192)

    // global->smem cp.async mapping (256 threads, 12 x 16B each):
    //  X: thread (r = tid>>1, q = tid&1) loads X[r, q*32 .. q*32+31]  (4 CP16)
    //  W: thread tid loads full 64-elem k-row of W[n0+tid]            (8 CP16)
    const int r_ld = tid >> 1;
    const int q_ld = tid & 1;
    const int m_ld = m0 + r_ld;
    const int tok  = (m_ld < cnt) ? g_sorted_idx[seg_lo + m_ld] : g_sorted_idx[seg_lo];
    const __half* pX = g_xf + (size_t)tok * DIM + q_ld * 32;
    const __half* pW = g_w1f + ((size_t)e * HID + n0 + tid) * DIM;
    const uint32_t dX_off = (uint32_t)(r_ld * SPAD + q_ld * 32) * 2;   // bytes
    const uint32_t dW_off = (uint32_t)(tid * SPAD) * 2;

    // ldmatrix lane addressing (byte offsets within a stage; row stride 144B)
    const int a_row = wm + (lane & 15);
    const int a_kb  = (lane >> 4) * 16;
    const int b_row = wn + ((lane >> 4) & 1) * 8 + (lane & 7);
    const int b_kb  = ((lane >> 3) & 1) * 16;

    float acc[4][8][4];
    #pragma unroll
    for (int i = 0; i < 4; i++)
        #pragma unroll
        for (int j = 0; j < 8; j++)
            #pragma unroll
            for (int q = 0; q < 4; q++) acc[i][j][q] = 0.f;

    auto issue = [&](int c, int st) {
        const int kg = c * BK;
        const uint32_t sb = smem0 + st * STAGE_BYTES;
        #pragma unroll
        for (int u = 0; u < 4; u++)
            CP16(sb + dX_off + u * 16, pX + kg + u * 8);
        #pragma unroll
        for (int u = 0; u < 8; u++)
            CP16(sb + ST_W * 2 + dW_off + u * 16, pW + kg + u * 8);
        CP_COMMIT();
    };

    issue(0, 0);
    issue(1, 1);

    int st = 0;
    for (int c = 0; c < NITER; c++) {
        if (c + 2 <= NITER - 1) { asm volatile("cp.async.wait_group 1;" ::: "memory"); }
        else                    { asm volatile("cp.async.wait_group 0;" ::: "memory"); }
        __syncthreads();

        if (c + 2 < NITER) {
            int st2 = st + 2; if (st2 >= NSTAGE) st2 -= NSTAGE;
            issue(c + 2, st2);
        }

        const uint32_t sb = smem0 + st * STAGE_BYTES;
        const uint32_t bX = sb;
        const uint32_t bW = sb + ST_W * 2;

        #pragma unroll
        for (int ks = 0; ks < 4; ks++) {
            uint32_t fx[4][4], fw[8][2];
            #pragma unroll
            for (int mt = 0; mt < 4; mt++) {
                uint32_t oa = (uint32_t)((a_row + mt * 16) * (SPAD * 2) + ks * 32 + a_kb);
                LDMX4(fx[mt][0], fx[mt][1], fx[mt][2], fx[mt][3], bX + oa);
            }
            #pragma unroll
            for (int p = 0; p < 4; p++) {
                uint32_t ob = (uint32_t)((b_row + p * 16) * (SPAD * 2) + ks * 32 + b_kb);
                LDMX4(fw[2 * p][0], fw[2 * p][1], fw[2 * p + 1][0], fw[2 * p + 1][1], bW + ob);
            }
            #pragma unroll
            for (int mt = 0; mt < 4; mt++)
                #pragma unroll
                for (int nt = 0; nt < 8; nt++)
                    MMAF16(acc[mt][nt], fx[mt], fw[nt]);
        }

        st = st + 1; if (st >= NSTAGE) st -= NSTAGE;
    }

    // epilogue: bias + ReLU, half2 stores to g_h16 (sorted layout)
    #pragma unroll
    for (int nt = 0; nt < 8; nt++) {
        const int ncol = n0 + wn + nt * 8 + (lane & 3) * 2;
        const float bia0 = b1[e * HID + ncol];
        const float bia1 = b1[e * HID + ncol + 1];
        #pragma unroll
        for (int mt = 0; mt < 4; mt++) {
            int r0 = wm + mt * 16 + (lane >> 2);
            int ma = m0 + r0;
            if (ma < cnt) {
                float v0 = fmaxf(acc[mt][nt][0] + bia0, 0.f);
                float v1 = fmaxf(acc[mt][nt][1] + bia1, 0.f);
                *(__half2*)(g_h16 + (size_t)(seg_lo + ma) * HID + ncol) =
                    __floats2half2_rn(v0, v1);
            }
            int mb = ma + 8;
            if (mb < cnt) {
                float v0 = fmaxf(acc[mt][nt][2] + bia0, 0.f);
                float v1 = fmaxf(acc[mt][nt][3] + bia1, 0.f);
                *(__half2*)(g_h16 + (size_t)(seg_lo + mb) * HID + ncol) =
                    __floats2half2_rn(v0, v1);
            }
        }
    }
}

// -------- kernel 4: out[tok] = h_sorted[s] @ W2[e] + b2[e], one warp per token --------
__global__ __launch_bounds__(256) void k_gemm2(
    const float* __restrict__ W2,
    const float* __restrict__ b2,
    float* __restrict__ out)
{
    int gwarp = (blockIdx.x * blockDim.x + threadIdx.x) >> 5;
    int lane  = threadIdx.x & 31;
    if (gwarp >= NTOK) return;
    int s   = gwarp;
    int e   = g_sorted_expert[s];
    int tok = g_sorted_idx[s];
    const __half2* hrow = (const __half2*)(g_h16 + (size_t)s * HID);   // 384 half2
    const float*   w2   = W2 + (size_t)e * HID * COUT;

    float a0 = 0.f, a1 = 0.f;
    #pragma unroll 4
    for (int i = lane; i < HID / 2; i += 32) {
        float2 hv = __half22float2(hrow[i]);
        float4 w = *(const float4*)(w2 + i * 4);
        a0 = fmaf(hv.x, w.x, a0);
        a1 = fmaf(hv.x, w.y, a1);
        a0 = fmaf(hv.y, w.z, a0);
        a1 = fmaf(hv.y, w.w, a1);
    }
    #pragma unroll
    for (int o = 16; o > 0; o >>= 1) {
        a0 += __shfl_xor_sync(0xFFFFFFFFu, a0, o);
        a1 += __shfl_xor_sync(0xFFFFFFFFu, a1, o);
    }
    if (lane == 0) {
        out[tok * 2 + 0] = a0 + b2[e * 2 + 0];
        out[tok * 2 + 1] = a1 + b2[e * 2 + 1];
    }
}

extern "C" void kernel_launch(void* const* d_in, const int* in_sizes, int n_in,
                              void* d_out, int out_size) {
    const float* X   = (const float*)d_in[0];      // [N, D]
    const void*  cid = d_in[1];                    // [N] int32 or int64
    const float* W1  = (const float*)d_in[2];      // [E, D, H]
    const float* b1  = (const float*)d_in[3];      // [E, H]
    const float* W2  = (const float*)d_in[4];      // [E, H, C]
    const float* b2  = (const float*)d_in[5];      // [E, C]
    float*       out = (float*)d_out;              // [N, C]

    cudaFuncSetAttribute(k_gemm1, cudaFuncAttributeMaxDynamicSharedMemorySize, SMEM_TOTAL);

    k_prep<<<1, 1024>>>((const int*)cid);
    k_convert_x<<<(int)(((size_t)NTOK * DIM / 4 + 255) / 256), 256>>>(X);
    k_split_w1<<<dim3(HID / 32, DIM / 32, NEXP), dim3(32, 8)>>>(W1);

    dim3 grid1(HID / BN, NTOK / BM, NEXP);
    k_gemm1<<<grid1, 256, SMEM_TOTAL>>>(b1);

    k_gemm2<<<(NTOK * 32 + 255) / 256, 256>>>(W2, b2, out);
}